// round 1
// baseline (speedup 1.0000x reference)
#include <cuda_runtime.h>

// PolynomialLossNaive: loss = ||F^T F - S^T S||_F^2 / (hw^2 * ch^2)
// F = input reshaped [ch=64, hw=8192] (channel-major), same for S=target.
// Gram difference D[c][c'] = sum_i F[c][i]*F[c'][i] - S[c][i]*S[c'][i]  (64x64),
// then sum(D^2) * 2^-38.

#define CH   64
#define HW   8192
#define IPB  64          // i-values per block
#define NBLK (HW / IPB)  // 128
#define GELEM (CH * CH)  // 4096

__device__ float g_partials[NBLK * GELEM];  // per-block Gram-diff partials
__device__ float g_sq[32];                  // per-block squared-sum partials

__global__ void __launch_bounds__(256) gram_diff_kernel(const float* __restrict__ A,
                                                        const float* __restrict__ B) {
    // SMEM staged i-major with 16B-group XOR swizzle: element (c, ii) lives at
    // column 4*((c>>2) ^ (ii&15)) + (c&3). Reads below are conflict-free LDS.128.
    __shared__ __align__(16) float fsh[IPB][CH];
    __shared__ __align__(16) float ssh[IPB][CH];

    const int tid = threadIdx.x;
    const int i0  = blockIdx.x * IPB;

    // Load 64 c-rows x 64 i-values for both matrices: fully coalesced float4.
#pragma unroll
    for (int r = 0; r < 4; ++r) {
        int idx = r * 256 + tid;      // 0..1023
        int c   = idx >> 4;           // 0..63
        int g   = idx & 15;           // float4 group along i
        const float4 fv = *reinterpret_cast<const float4*>(A + (size_t)c * HW + i0 + 4 * g);
        const float4 sv = *reinterpret_cast<const float4*>(B + (size_t)c * HW + i0 + 4 * g);
        const int cg = c >> 2, cl = c & 3;
        float fvals[4] = {fv.x, fv.y, fv.z, fv.w};
        float svals[4] = {sv.x, sv.y, sv.z, sv.w};
#pragma unroll
        for (int k = 0; k < 4; ++k) {
            int ii  = 4 * g + k;
            int col = 4 * (cg ^ (ii & 15)) + cl;
            fsh[ii][col] = fvals[k];
            ssh[ii][col] = svals[k];
        }
    }
    __syncthreads();

    // 16x16 thread grid, each thread owns a 4x4 tile of the 64x64 Gram diff.
    const int tx = tid & 15;
    const int ty = tid >> 4;

    float acc[4][4];
#pragma unroll
    for (int a = 0; a < 4; ++a)
#pragma unroll
        for (int b = 0; b < 4; ++b) acc[a][b] = 0.0f;

#pragma unroll
    for (int ii = 0; ii < IPB; ++ii) {
        const int sw = ii & 15;
        // fa broadcast across the 16 tx lanes; fb spans the full 256B row: conflict-free.
        float4 fa4 = *reinterpret_cast<float4*>(&fsh[ii][4 * (ty ^ sw)]);
        float4 fb4 = *reinterpret_cast<float4*>(&fsh[ii][4 * (tx ^ sw)]);
        float4 sa4 = *reinterpret_cast<float4*>(&ssh[ii][4 * (ty ^ sw)]);
        float4 sb4 = *reinterpret_cast<float4*>(&ssh[ii][4 * (tx ^ sw)]);
        float fa[4] = {fa4.x, fa4.y, fa4.z, fa4.w};
        float fb[4] = {fb4.x, fb4.y, fb4.z, fb4.w};
        float sa[4] = {sa4.x, sa4.y, sa4.z, sa4.w};
        float sb[4] = {sb4.x, sb4.y, sb4.z, sb4.w};
#pragma unroll
        for (int a = 0; a < 4; ++a)
#pragma unroll
            for (int b = 0; b < 4; ++b) {
                acc[a][b] = fmaf(fa[a], fb[b], acc[a][b]);
                acc[a][b] = fmaf(-sa[a], sb[b], acc[a][b]);
            }
    }

    // Deterministic per-block partial write (coalesced).
    float* p = g_partials + (size_t)blockIdx.x * GELEM;
#pragma unroll
    for (int a = 0; a < 4; ++a)
#pragma unroll
        for (int b = 0; b < 4; ++b)
            p[(4 * ty + a) * CH + (4 * tx + b)] = acc[a][b];
}

__global__ void __launch_bounds__(128) reduce1_kernel() {
    // 32 blocks x 128 threads: thread -> one Gram entry e; sum 128 partials, square.
    const int e = blockIdx.x * 128 + threadIdx.x;  // 0..4095
    float s = 0.0f;
#pragma unroll 8
    for (int b = 0; b < NBLK; ++b) s += g_partials[b * GELEM + e];
    float sq = s * s;

    // warp reduce
#pragma unroll
    for (int off = 16; off > 0; off >>= 1)
        sq += __shfl_down_sync(0xffffffffu, sq, off);

    __shared__ float wsum[4];
    if ((threadIdx.x & 31) == 0) wsum[threadIdx.x >> 5] = sq;
    __syncthreads();
    if (threadIdx.x == 0)
        g_sq[blockIdx.x] = wsum[0] + wsum[1] + wsum[2] + wsum[3];
}

__global__ void __launch_bounds__(32) reduce2_kernel(float* __restrict__ out) {
    float v = g_sq[threadIdx.x];
#pragma unroll
    for (int off = 16; off > 0; off >>= 1)
        v += __shfl_down_sync(0xffffffffu, v, off);
    if (threadIdx.x == 0)
        out[0] = v * (1.0f / 274877906944.0f);  // / (8192^2 * 64^2) = 2^-38, exact
}

extern "C" void kernel_launch(void* const* d_in, const int* in_sizes, int n_in,
                              void* d_out, int out_size) {
    const float* A = (const float*)d_in[0];  // input  [1,64,128,64] -> [64, 8192]
    const float* B = (const float*)d_in[1];  // target [1,64,128,64] -> [64, 8192]
    float* out = (float*)d_out;

    gram_diff_kernel<<<NBLK, 256>>>(A, B);
    reduce1_kernel<<<32, 128>>>();
    reduce2_kernel<<<1, 32>>>(out);
}